// round 2
// baseline (speedup 1.0000x reference)
#include <cuda_runtime.h>
#include <math.h>

#define NB 2
#define NH 64
#define NW 64
#define NC 256
#define NQ 4096
#define NK 49
#define NLEV 4

// Pyramid scratch (cascaded, un-normalized) + normalized features per level.
__device__ float g_pyr1[NB*32*32*NC];
__device__ float g_pyr2[NB*16*16*NC];
__device__ float g_pyr3[NB*8*8*NC];
__device__ float g_f2n0[NB*64*64*NC];
__device__ float g_f2n1[NB*32*32*NC];
__device__ float g_f2n2[NB*16*16*NC];
__device__ float g_f2n3[NB*8*8*NC];

// jax.image.resize(method='bilinear', antialias=True) 2x downsample taps.
// For output i over input size n: sample center c = 2i + 0.5, triangle kernel
// scaled by 2, support j in [2i-1, 2i+2], weights renormalized over valid taps.
__device__ __forceinline__ void resize_taps(int i, int n, int jj[4], float ww[4]) {
    float c = 2.0f * (float)i + 0.5f;
    float s = 0.0f;
#pragma unroll
    for (int t = 0; t < 4; t++) {
        int j = 2 * i - 1 + t;
        float w = 0.0f;
        if (j >= 0 && j < n) w = 1.0f - 0.5f * fabsf(c - (float)j);
        jj[t] = j < 0 ? 0 : (j > n - 1 ? n - 1 : j);
        ww[t] = w;
        s += w;
    }
    float inv = 1.0f / s;
#pragma unroll
    for (int t = 0; t < 4; t++) ww[t] *= inv;
}

__global__ void downsample_kernel(const float* __restrict__ in, float* __restrict__ out,
                                  int Hi, int Wi) {
    int Ho = Hi >> 1, Wo = Wi >> 1;
    int p = blockIdx.x;
    int b = blockIdx.y;
    int yo = p / Wo, xo = p % Wo;
    int c = threadIdx.x;
    int jy[4], jx[4];
    float wy[4], wx[4];
    resize_taps(yo, Hi, jy, wy);
    resize_taps(xo, Wi, jx, wx);
    const float* ib = in + (size_t)b * Hi * Wi * NC;
    float acc = 0.0f;
#pragma unroll
    for (int a = 0; a < 4; a++) {
        float r = 0.0f;
#pragma unroll
        for (int t = 0; t < 4; t++)
            r += wx[t] * ib[((size_t)jy[a] * Wi + jx[t]) * NC + c];
        acc += wy[a] * r;
    }
    out[(((size_t)b * Ho + yo) * Wo + xo) * NC + c] = acc;
}

// Per-pixel L2 normalize over C=256 (one block per pixel, 256 threads).
__global__ void normalize_kernel(const float* __restrict__ in, float* __restrict__ out, int HW) {
    int p = blockIdx.x, b = blockIdx.y;
    size_t off = ((size_t)b * HW + p) * NC + threadIdx.x;
    float x = in[off];
    __shared__ float red[8];
    __shared__ float sc;
    float s = x * x;
#pragma unroll
    for (int o = 16; o > 0; o >>= 1) s += __shfl_xor_sync(0xffffffffu, s, o);
    if ((threadIdx.x & 31) == 0) red[threadIdx.x >> 5] = s;
    __syncthreads();
    if (threadIdx.x == 0) {
        float t = 0.0f;
#pragma unroll
        for (int i = 0; i < 8; i++) t += red[i];
        sc = 1.0f / (sqrtf(t) + 1e-6f);
    }
    __syncthreads();
    out[off] = x * sc;
}

// Main kernel: one block per (b, n) query. 256 threads.
// Stage A: feat1 = normalize(bilinear(fmap1, coords1)) into smem.
// Stage B (per level): D[8][8] = dot(feat1, f2n[window]) via warp-per-position
//                      reductions; then 49 outputs from scalar bilinear weights.
__global__ void __launch_bounds__(256) corr_kernel(
    const float* __restrict__ fmap1,
    const float* __restrict__ coords1,
    const float* __restrict__ coords2,
    const float* __restrict__ f2n0,
    const float* __restrict__ f2n1,
    const float* __restrict__ f2n2,
    const float* __restrict__ f2n3,
    float* __restrict__ out) {
    int b = blockIdx.y;
    int n = blockIdx.x;
    int tid = threadIdx.x;
    int lane = tid & 31, wid = tid >> 5;

    __shared__ float feat1[NC];
    __shared__ float D[64];
    __shared__ float red[8];
    __shared__ float sscale;

    // ---- Stage A: feat1 ----
    float cx = coords1[((size_t)b * NQ + n) * 2 + 0];
    float cy = coords1[((size_t)b * NQ + n) * 2 + 1];
    int fx0 = (int)floorf(cx);
    int fy0 = (int)floorf(cy);
    int x0 = min(max(fx0, 0), NW - 1);
    int x1 = min(max(fx0 + 1, 0), NW - 1);
    int y0 = min(max(fy0, 0), NH - 1);
    int y1 = min(max(fy0 + 1, 0), NH - 1);
    float x0f = (float)x0, x1f = (float)x1, y0f = (float)y0, y1f = (float)y1;
    float wa = (x1f - cx) * (y1f - cy);
    float wb = (x1f - cx) * (cy - y0f);
    float wc = (cx - x0f) * (y1f - cy);
    float wd = (cx - x0f) * (cy - y0f);
    const float* fb1 = fmap1 + (size_t)b * NH * NW * NC;
    float v = wa * fb1[((size_t)y0 * NW + x0) * NC + tid] +
              wb * fb1[((size_t)y1 * NW + x0) * NC + tid] +
              wc * fb1[((size_t)y0 * NW + x1) * NC + tid] +
              wd * fb1[((size_t)y1 * NW + x1) * NC + tid];
    float s = v * v;
#pragma unroll
    for (int o = 16; o > 0; o >>= 1) s += __shfl_xor_sync(0xffffffffu, s, o);
    if (lane == 0) red[wid] = s;
    __syncthreads();
    if (tid == 0) {
        float t = 0.0f;
#pragma unroll
        for (int i = 0; i < 8; i++) t += red[i];
        sscale = 1.0f / (sqrtf(t) + 1e-6f);
    }
    __syncthreads();
    feat1[tid] = v * sscale;
    __syncthreads();

    float qx = coords2[((size_t)b * NQ + n) * 2 + 0];
    float qy = coords2[((size_t)b * NQ + n) * 2 + 1];

    const float* levels[NLEV] = {f2n0, f2n1, f2n2, f2n3};

#pragma unroll
    for (int l = 0; l < NLEV; l++) {
        const int Hl = NH >> l, Wl = NW >> l;
        const float* f2n = levels[l];
        const float scl = (float)(1 << l);
        float bx = qx / scl;
        float by = qy / scl;
        int ix = (int)floorf(bx);
        int iy = (int)floorf(by);

        // ---- D table: 64 window dots, 8 positions per warp ----
        const float* fb = f2n + (size_t)b * Hl * Wl * NC;
        const float4* f1p = (const float4*)feat1;
        float4 q0 = f1p[lane];
        float4 q1 = f1p[lane + 32];
#pragma unroll
        for (int pp = 0; pp < 8; pp++) {
            int p = wid * 8 + pp;       // warp `wid` owns window row `wid`
            int wi = p >> 3, wj = p & 7;
            int yy = min(max(iy - 3 + wi, 0), Hl - 1);
            int xx = min(max(ix - 3 + wj, 0), Wl - 1);
            const float4* rowp = (const float4*)(fb + ((size_t)yy * Wl + xx) * NC);
            float4 a0 = rowp[lane];
            float4 a1 = rowp[lane + 32];
            float acc = a0.x * q0.x + a0.y * q0.y + a0.z * q0.z + a0.w * q0.w +
                        a1.x * q1.x + a1.y * q1.y + a1.z * q1.z + a1.w * q1.w;
#pragma unroll
            for (int o = 16; o > 0; o >>= 1) acc += __shfl_xor_sync(0xffffffffu, acc, o);
            if (lane == 0) D[p] = acc;
        }
        __syncthreads();

        // ---- 49 outputs: scalar bilinear blend of D ----
        if (tid < NK) {
            int dy = tid / 7 - 3;   // offs is dy-major (meshgrid 'ij', raveled)
            int dx = tid % 7 - 3;
            float xk = fminf(fmaxf(bx + (float)dx, 0.0f), (float)(Wl - 1));
            float yk = fminf(fmaxf(by + (float)dy, 0.0f), (float)(Hl - 1));
            float fx = floorf(xk), fy = floorf(yk);
            float xh = fminf(fx + 1.0f, (float)(Wl - 1));
            float yh = fminf(fy + 1.0f, (float)(Hl - 1));
            // Weights from CLIPPED corner indices (reproduces the border-zero quirk).
            float wx1 = xk - fx, wx0 = xh - xk;
            float wy1 = yk - fy, wy0 = yh - yk;
            int jx0 = dx + 3, jx1 = dx + 4;
            int jy0 = dy + 3, jy1 = dy + 4;
            float val = wx0 * wy0 * D[jy0 * 8 + jx0] + wx0 * wy1 * D[jy1 * 8 + jx0] +
                        wx1 * wy0 * D[jy0 * 8 + jx1] + wx1 * wy1 * D[jy1 * 8 + jx1];
            out[((size_t)b * NQ + n) * (NLEV * NK) + l * NK + tid] = val;
        }
        __syncthreads();  // protect D before next level overwrites it
    }
}

extern "C" void kernel_launch(void* const* d_in, const int* in_sizes, int n_in,
                              void* d_out, int out_size) {
    const float* fmap1   = (const float*)d_in[0];
    const float* fmap2   = (const float*)d_in[1];
    const float* coords1 = (const float*)d_in[2];
    const float* coords2 = (const float*)d_in[3];
    float* out = (float*)d_out;

    float *pyr1, *pyr2, *pyr3, *f2n0, *f2n1, *f2n2, *f2n3;
    cudaGetSymbolAddress((void**)&pyr1, g_pyr1);
    cudaGetSymbolAddress((void**)&pyr2, g_pyr2);
    cudaGetSymbolAddress((void**)&pyr3, g_pyr3);
    cudaGetSymbolAddress((void**)&f2n0, g_f2n0);
    cudaGetSymbolAddress((void**)&f2n1, g_f2n1);
    cudaGetSymbolAddress((void**)&f2n2, g_f2n2);
    cudaGetSymbolAddress((void**)&f2n3, g_f2n3);

    // Cascaded pyramid (un-normalized), matching jax.image.resize antialiased bilinear.
    downsample_kernel<<<dim3(32 * 32, NB), 256>>>(fmap2, pyr1, 64, 64);
    downsample_kernel<<<dim3(16 * 16, NB), 256>>>(pyr1, pyr2, 32, 32);
    downsample_kernel<<<dim3(8 * 8, NB), 256>>>(pyr2, pyr3, 16, 16);

    // Per-level L2 normalization.
    normalize_kernel<<<dim3(64 * 64, NB), 256>>>(fmap2, f2n0, 64 * 64);
    normalize_kernel<<<dim3(32 * 32, NB), 256>>>(pyr1, f2n1, 32 * 32);
    normalize_kernel<<<dim3(16 * 16, NB), 256>>>(pyr2, f2n2, 16 * 16);
    normalize_kernel<<<dim3(8 * 8, NB), 256>>>(pyr3, f2n3, 8 * 8);

    // Main correlation kernel: one block per (b, n).
    corr_kernel<<<dim3(NQ, NB), 256>>>(fmap1, coords1, coords2,
                                       f2n0, f2n1, f2n2, f2n3, out);
}

// round 3
// speedup vs baseline: 1.0102x; 1.0102x over previous
#include <cuda_runtime.h>
#include <math.h>

#define NB 2
#define NH 64
#define NW 64
#define NC 256
#define NQ 4096
#define NK 49
#define NLEV 4

// Pyramid scratch (cascaded, un-normalized) + normalized features per level.
__device__ float g_pyr1[NB*32*32*NC];
__device__ float g_pyr2[NB*16*16*NC];
__device__ float g_pyr3[NB*8*8*NC];
__device__ float g_f2n0[NB*64*64*NC];
__device__ float g_f2n1[NB*32*32*NC];
__device__ float g_f2n2[NB*16*16*NC];
__device__ float g_f2n3[NB*8*8*NC];

// jax.image.resize(method='bilinear', antialias=True) 2x downsample taps.
// For output i over input size n: sample center c = 2i + 0.5, triangle kernel
// scaled by 2, support j in [2i-1, 2i+2], weights renormalized over valid taps.
__device__ __forceinline__ void resize_taps(int i, int n, int jj[4], float ww[4]) {
    float c = 2.0f * (float)i + 0.5f;
    float s = 0.0f;
#pragma unroll
    for (int t = 0; t < 4; t++) {
        int j = 2 * i - 1 + t;
        float w = 0.0f;
        if (j >= 0 && j < n) w = 1.0f - 0.5f * fabsf(c - (float)j);
        jj[t] = j < 0 ? 0 : (j > n - 1 ? n - 1 : j);
        ww[t] = w;
        s += w;
    }
    float inv = 1.0f / s;
#pragma unroll
    for (int t = 0; t < 4; t++) ww[t] *= inv;
}

__global__ void downsample_kernel(const float* __restrict__ in, float* __restrict__ out,
                                  int Hi, int Wi) {
    int Ho = Hi >> 1, Wo = Wi >> 1;
    int p = blockIdx.x;
    int b = blockIdx.y;
    int yo = p / Wo, xo = p % Wo;
    int c = threadIdx.x;
    int jy[4], jx[4];
    float wy[4], wx[4];
    resize_taps(yo, Hi, jy, wy);
    resize_taps(xo, Wi, jx, wx);
    const float* ib = in + (size_t)b * Hi * Wi * NC;
    float acc = 0.0f;
#pragma unroll
    for (int a = 0; a < 4; a++) {
        float r = 0.0f;
#pragma unroll
        for (int t = 0; t < 4; t++)
            r += wx[t] * ib[((size_t)jy[a] * Wi + jx[t]) * NC + c];
        acc += wy[a] * r;
    }
    out[(((size_t)b * Ho + yo) * Wo + xo) * NC + c] = acc;
}

// Per-pixel L2 normalize over C=256 (one block per pixel, 256 threads).
__global__ void normalize_kernel(const float* __restrict__ in, float* __restrict__ out, int HW) {
    int p = blockIdx.x, b = blockIdx.y;
    size_t off = ((size_t)b * HW + p) * NC + threadIdx.x;
    float x = in[off];
    __shared__ float red[8];
    __shared__ float sc;
    float s = x * x;
#pragma unroll
    for (int o = 16; o > 0; o >>= 1) s += __shfl_xor_sync(0xffffffffu, s, o);
    if ((threadIdx.x & 31) == 0) red[threadIdx.x >> 5] = s;
    __syncthreads();
    if (threadIdx.x == 0) {
        float t = 0.0f;
#pragma unroll
        for (int i = 0; i < 8; i++) t += red[i];
        sc = 1.0f / (sqrtf(t) + 1e-6f);
    }
    __syncthreads();
    out[off] = x * sc;
}

// Main kernel: one block per (b, n) query. 256 threads.
// Stage A: feat1 = normalize(bilinear(fmap1, coords1)) into smem.
// Stage B (per level): D[8][8] = dot(feat1, f2n[window]) via warp-per-position
//                      reductions; then 49 outputs from scalar bilinear weights.
__global__ void __launch_bounds__(256) corr_kernel(
    const float* __restrict__ fmap1,
    const float* __restrict__ coords1,
    const float* __restrict__ coords2,
    const float* __restrict__ f2n0,
    const float* __restrict__ f2n1,
    const float* __restrict__ f2n2,
    const float* __restrict__ f2n3,
    float* __restrict__ out) {
    int b = blockIdx.y;
    int n = blockIdx.x;
    int tid = threadIdx.x;
    int lane = tid & 31, wid = tid >> 5;

    __shared__ float feat1[NC];
    __shared__ float D[64];
    __shared__ float red[8];
    __shared__ float sscale;

    // ---- Stage A: feat1 ----
    float cx = coords1[((size_t)b * NQ + n) * 2 + 0];
    float cy = coords1[((size_t)b * NQ + n) * 2 + 1];
    int fx0 = (int)floorf(cx);
    int fy0 = (int)floorf(cy);
    int x0 = min(max(fx0, 0), NW - 1);
    int x1 = min(max(fx0 + 1, 0), NW - 1);
    int y0 = min(max(fy0, 0), NH - 1);
    int y1 = min(max(fy0 + 1, 0), NH - 1);
    float x0f = (float)x0, x1f = (float)x1, y0f = (float)y0, y1f = (float)y1;
    float wa = (x1f - cx) * (y1f - cy);
    float wb = (x1f - cx) * (cy - y0f);
    float wc = (cx - x0f) * (y1f - cy);
    float wd = (cx - x0f) * (cy - y0f);
    const float* fb1 = fmap1 + (size_t)b * NH * NW * NC;
    float v = wa * fb1[((size_t)y0 * NW + x0) * NC + tid] +
              wb * fb1[((size_t)y1 * NW + x0) * NC + tid] +
              wc * fb1[((size_t)y0 * NW + x1) * NC + tid] +
              wd * fb1[((size_t)y1 * NW + x1) * NC + tid];
    float s = v * v;
#pragma unroll
    for (int o = 16; o > 0; o >>= 1) s += __shfl_xor_sync(0xffffffffu, s, o);
    if (lane == 0) red[wid] = s;
    __syncthreads();
    if (tid == 0) {
        float t = 0.0f;
#pragma unroll
        for (int i = 0; i < 8; i++) t += red[i];
        sscale = 1.0f / (sqrtf(t) + 1e-6f);
    }
    __syncthreads();
    feat1[tid] = v * sscale;
    __syncthreads();

    float qx = coords2[((size_t)b * NQ + n) * 2 + 0];
    float qy = coords2[((size_t)b * NQ + n) * 2 + 1];

    const float* levels[NLEV] = {f2n0, f2n1, f2n2, f2n3};

#pragma unroll
    for (int l = 0; l < NLEV; l++) {
        const int Hl = NH >> l, Wl = NW >> l;
        const float* f2n = levels[l];
        const float scl = (float)(1 << l);
        float bx = qx / scl;
        float by = qy / scl;
        int ix = (int)floorf(bx);
        int iy = (int)floorf(by);

        // ---- D table: 64 window dots, 8 positions per warp ----
        const float* fb = f2n + (size_t)b * Hl * Wl * NC;
        const float4* f1p = (const float4*)feat1;
        float4 q0 = f1p[lane];
        float4 q1 = f1p[lane + 32];
#pragma unroll
        for (int pp = 0; pp < 8; pp++) {
            int p = wid * 8 + pp;       // warp `wid` owns window row `wid`
            int wi = p >> 3, wj = p & 7;
            int yy = min(max(iy - 3 + wi, 0), Hl - 1);
            int xx = min(max(ix - 3 + wj, 0), Wl - 1);
            const float4* rowp = (const float4*)(fb + ((size_t)yy * Wl + xx) * NC);
            float4 a0 = rowp[lane];
            float4 a1 = rowp[lane + 32];
            float acc = a0.x * q0.x + a0.y * q0.y + a0.z * q0.z + a0.w * q0.w +
                        a1.x * q1.x + a1.y * q1.y + a1.z * q1.z + a1.w * q1.w;
#pragma unroll
            for (int o = 16; o > 0; o >>= 1) acc += __shfl_xor_sync(0xffffffffu, acc, o);
            if (lane == 0) D[p] = acc;
        }
        __syncthreads();

        // ---- 49 outputs: scalar bilinear blend of D ----
        if (tid < NK) {
            int dy = tid / 7 - 3;   // offs is dy-major (meshgrid 'ij', raveled)
            int dx = tid % 7 - 3;
            float xk = fminf(fmaxf(bx + (float)dx, 0.0f), (float)(Wl - 1));
            float yk = fminf(fmaxf(by + (float)dy, 0.0f), (float)(Hl - 1));
            float fx = floorf(xk), fy = floorf(yk);
            float xh = fminf(fx + 1.0f, (float)(Wl - 1));
            float yh = fminf(fy + 1.0f, (float)(Hl - 1));
            // Weights from CLIPPED corner indices (reproduces the border-zero quirk).
            float wx1 = xk - fx, wx0 = xh - xk;
            float wy1 = yk - fy, wy0 = yh - yk;
            int jx0 = dx + 3, jx1 = dx + 4;
            int jy0 = dy + 3, jy1 = dy + 4;
            float val = wx0 * wy0 * D[jy0 * 8 + jx0] + wx0 * wy1 * D[jy1 * 8 + jx0] +
                        wx1 * wy0 * D[jy0 * 8 + jx1] + wx1 * wy1 * D[jy1 * 8 + jx1];
            out[((size_t)b * NQ + n) * (NLEV * NK) + l * NK + tid] = val;
        }
        __syncthreads();  // protect D before next level overwrites it
    }
}

extern "C" void kernel_launch(void* const* d_in, const int* in_sizes, int n_in,
                              void* d_out, int out_size) {
    const float* fmap1   = (const float*)d_in[0];
    const float* fmap2   = (const float*)d_in[1];
    const float* coords1 = (const float*)d_in[2];
    const float* coords2 = (const float*)d_in[3];
    float* out = (float*)d_out;

    float *pyr1, *pyr2, *pyr3, *f2n0, *f2n1, *f2n2, *f2n3;
    cudaGetSymbolAddress((void**)&pyr1, g_pyr1);
    cudaGetSymbolAddress((void**)&pyr2, g_pyr2);
    cudaGetSymbolAddress((void**)&pyr3, g_pyr3);
    cudaGetSymbolAddress((void**)&f2n0, g_f2n0);
    cudaGetSymbolAddress((void**)&f2n1, g_f2n1);
    cudaGetSymbolAddress((void**)&f2n2, g_f2n2);
    cudaGetSymbolAddress((void**)&f2n3, g_f2n3);

    // Cascaded pyramid (un-normalized), matching jax.image.resize antialiased bilinear.
    downsample_kernel<<<dim3(32 * 32, NB), 256>>>(fmap2, pyr1, 64, 64);
    downsample_kernel<<<dim3(16 * 16, NB), 256>>>(pyr1, pyr2, 32, 32);
    downsample_kernel<<<dim3(8 * 8, NB), 256>>>(pyr2, pyr3, 16, 16);

    // Per-level L2 normalization.
    normalize_kernel<<<dim3(64 * 64, NB), 256>>>(fmap2, f2n0, 64 * 64);
    normalize_kernel<<<dim3(32 * 32, NB), 256>>>(pyr1, f2n1, 32 * 32);
    normalize_kernel<<<dim3(16 * 16, NB), 256>>>(pyr2, f2n2, 16 * 16);
    normalize_kernel<<<dim3(8 * 8, NB), 256>>>(pyr3, f2n3, 8 * 8);

    // Main correlation kernel: one block per (b, n).
    corr_kernel<<<dim3(NQ, NB), 256>>>(fmap1, coords1, coords2,
                                       f2n0, f2n1, f2n2, f2n3, out);
}

// round 5
// speedup vs baseline: 1.2089x; 1.1967x over previous
#include <cuda_runtime.h>
#include <cuda_fp16.h>
#include <math.h>

#define NB 2
#define NH 64
#define NW 64
#define NC 256
#define NQ 4096
#define NK 49
#define NLEV 4

// Pyramid scratch (cascaded, un-normalized, fp32) + normalized fp16 features per level.
__device__ float  g_pyr1[NB*32*32*NC];
__device__ float  g_pyr2[NB*16*16*NC];
__device__ float  g_pyr3[NB*8*8*NC];
__device__ __half g_h0[NB*64*64*NC];
__device__ __half g_h1[NB*32*32*NC];
__device__ __half g_h2[NB*16*16*NC];
__device__ __half g_h3[NB*8*8*NC];

__device__ __forceinline__ unsigned int h2_as_u32(__half2 h) {
    return *reinterpret_cast<unsigned int*>(&h);
}

// jax.image.resize(method='bilinear', antialias=True) 2x downsample taps.
__device__ __forceinline__ void resize_taps(int i, int n, int jj[4], float ww[4]) {
    float c = 2.0f * (float)i + 0.5f;
    float s = 0.0f;
#pragma unroll
    for (int t = 0; t < 4; t++) {
        int j = 2 * i - 1 + t;
        float w = 0.0f;
        if (j >= 0 && j < n) w = 1.0f - 0.5f * fabsf(c - (float)j);
        jj[t] = j < 0 ? 0 : (j > n - 1 ? n - 1 : j);
        ww[t] = w;
        s += w;
    }
    float inv = 1.0f / s;
#pragma unroll
    for (int t = 0; t < 4; t++) ww[t] *= inv;
}

__global__ void downsample_kernel(const float* __restrict__ in, float* __restrict__ out,
                                  int Hi, int Wi) {
    int Ho = Hi >> 1, Wo = Wi >> 1;
    int p = blockIdx.x;
    int b = blockIdx.y;
    int yo = p / Wo, xo = p % Wo;
    int c = threadIdx.x;
    int jy[4], jx[4];
    float wy[4], wx[4];
    resize_taps(yo, Hi, jy, wy);
    resize_taps(xo, Wi, jx, wx);
    const float* ib = in + (size_t)b * Hi * Wi * NC;
    float acc = 0.0f;
#pragma unroll
    for (int a = 0; a < 4; a++) {
        float r = 0.0f;
#pragma unroll
        for (int t = 0; t < 4; t++)
            r += wx[t] * ib[((size_t)jy[a] * Wi + jx[t]) * NC + c];
        acc += wy[a] * r;
    }
    out[(((size_t)b * Ho + yo) * Wo + xo) * NC + c] = acc;
}

// Warp-per-pixel L2 normalize, fp32 in -> fp16 out. 8 pixels per 256-thread block.
__global__ void __launch_bounds__(256) normalize_h_kernel(
    const float* __restrict__ in, __half* __restrict__ out, int HW) {
    int warp = threadIdx.x >> 5, lane = threadIdx.x & 31;
    int p = blockIdx.x * 8 + warp;
    int b = blockIdx.y;
    size_t base = ((size_t)b * HW + p) * NC;
    const float4* ip = (const float4*)(in + base);
    float4 a0 = ip[lane * 2];
    float4 a1 = ip[lane * 2 + 1];
    float s = a0.x*a0.x + a0.y*a0.y + a0.z*a0.z + a0.w*a0.w +
              a1.x*a1.x + a1.y*a1.y + a1.z*a1.z + a1.w*a1.w;
#pragma unroll
    for (int o = 16; o > 0; o >>= 1) s += __shfl_xor_sync(0xffffffffu, s, o);
    float inv = 1.0f / (sqrtf(s) + 1e-6f);
    __half2 h0 = __floats2half2_rn(a0.x * inv, a0.y * inv);
    __half2 h1 = __floats2half2_rn(a0.z * inv, a0.w * inv);
    __half2 h2 = __floats2half2_rn(a1.x * inv, a1.y * inv);
    __half2 h3 = __floats2half2_rn(a1.z * inv, a1.w * inv);
    uint4 pk;
    pk.x = h2_as_u32(h0); pk.y = h2_as_u32(h1);
    pk.z = h2_as_u32(h2); pk.w = h2_as_u32(h3);
    ((uint4*)(out + base))[lane] = pk;
}

// Main kernel: one block per (b, n) query. 256 threads.
__global__ void __launch_bounds__(256) corr_kernel(
    const float* __restrict__ fmap1,
    const float* __restrict__ coords1,
    const float* __restrict__ coords2,
    const __half* __restrict__ f2n0,
    const __half* __restrict__ f2n1,
    const __half* __restrict__ f2n2,
    const __half* __restrict__ f2n3,
    float* __restrict__ out) {
    int b = blockIdx.y;
    int n = blockIdx.x;
    int tid = threadIdx.x;
    int lane = tid & 31, wid = tid >> 5;

    __shared__ float feat1[NC];
    __shared__ float D[64];
    __shared__ float red[8];
    __shared__ float sscale;

    // ---- Stage A: feat1 = normalize(bilinear(fmap1, coords1)) ----
    float cx = coords1[((size_t)b * NQ + n) * 2 + 0];
    float cy = coords1[((size_t)b * NQ + n) * 2 + 1];
    int fx0 = (int)floorf(cx);
    int fy0 = (int)floorf(cy);
    int x0 = min(max(fx0, 0), NW - 1);
    int x1 = min(max(fx0 + 1, 0), NW - 1);
    int y0 = min(max(fy0, 0), NH - 1);
    int y1 = min(max(fy0 + 1, 0), NH - 1);
    float x0f = (float)x0, x1f = (float)x1, y0f = (float)y0, y1f = (float)y1;
    float wa = (x1f - cx) * (y1f - cy);
    float wb = (x1f - cx) * (cy - y0f);
    float wc = (cx - x0f) * (y1f - cy);
    float wd = (cx - x0f) * (cy - y0f);
    const float* fb1 = fmap1 + (size_t)b * NH * NW * NC;
    float v = wa * fb1[((size_t)y0 * NW + x0) * NC + tid] +
              wb * fb1[((size_t)y1 * NW + x0) * NC + tid] +
              wc * fb1[((size_t)y0 * NW + x1) * NC + tid] +
              wd * fb1[((size_t)y1 * NW + x1) * NC + tid];
    float s = v * v;
#pragma unroll
    for (int o = 16; o > 0; o >>= 1) s += __shfl_xor_sync(0xffffffffu, s, o);
    if (lane == 0) red[wid] = s;
    __syncthreads();
    if (tid == 0) {
        float t = 0.0f;
#pragma unroll
        for (int i = 0; i < 8; i++) t += red[i];
        sscale = 1.0f / (sqrtf(t) + 1e-6f);
    }
    __syncthreads();
    feat1[tid] = v * sscale;
    __syncthreads();

    float qx = coords2[((size_t)b * NQ + n) * 2 + 0];
    float qy = coords2[((size_t)b * NQ + n) * 2 + 1];

    const __half* levels[NLEV] = {f2n0, f2n1, f2n2, f2n3};

    // Per-lane query slice: channels lane*8 .. lane*8+7 (hoisted out of level loop).
    float q[8];
    {
        const float4* f1p = (const float4*)feat1;
        float4 t0 = f1p[lane * 2];
        float4 t1 = f1p[lane * 2 + 1];
        q[0] = t0.x; q[1] = t0.y; q[2] = t0.z; q[3] = t0.w;
        q[4] = t1.x; q[5] = t1.y; q[6] = t1.z; q[7] = t1.w;
    }

#pragma unroll
    for (int l = 0; l < NLEV; l++) {
        const int Hl = NH >> l, Wl = NW >> l;
        const __half* f2n = levels[l];
        const float inv_scl = 1.0f / (float)(1 << l);
        float bx = qx * inv_scl;
        float by = qy * inv_scl;
        int ix = (int)floorf(bx);
        int iy = (int)floorf(by);

        // ---- D table: 64 window dots, warp `wid` owns window row `wid` ----
        const __half* fb = f2n + (size_t)b * Hl * Wl * NC;
        int yy = min(max(iy - 3 + wid, 0), Hl - 1);
#pragma unroll
        for (int wj = 0; wj < 8; wj++) {
            int xx = min(max(ix - 3 + wj, 0), Wl - 1);
            const uint4* rowp = (const uint4*)(fb + ((size_t)yy * Wl + xx) * NC);
            uint4 r = rowp[lane];   // 8 halves = channels lane*8..lane*8+7
            float2 f0 = __half22float2(*(const __half2*)&r.x);
            float2 f1 = __half22float2(*(const __half2*)&r.y);
            float2 f2 = __half22float2(*(const __half2*)&r.z);
            float2 f3 = __half22float2(*(const __half2*)&r.w);
            float acc = f0.x*q[0] + f0.y*q[1] + f1.x*q[2] + f1.y*q[3] +
                        f2.x*q[4] + f2.y*q[5] + f3.x*q[6] + f3.y*q[7];
#pragma unroll
            for (int o = 16; o > 0; o >>= 1) acc += __shfl_xor_sync(0xffffffffu, acc, o);
            if (lane == 0) D[wid * 8 + wj] = acc;
        }
        __syncthreads();

        // ---- 49 outputs: scalar bilinear blend of D ----
        if (tid < NK) {
            int dy = tid / 7 - 3;   // offs is dy-major
            int dx = tid % 7 - 3;
            float xk = fminf(fmaxf(bx + (float)dx, 0.0f), (float)(Wl - 1));
            float yk = fminf(fmaxf(by + (float)dy, 0.0f), (float)(Hl - 1));
            float fx = floorf(xk), fy = floorf(yk);
            float xh = fminf(fx + 1.0f, (float)(Wl - 1));
            float yh = fminf(fy + 1.0f, (float)(Hl - 1));
            float wx1 = xk - fx, wx0 = xh - xk;
            float wy1 = yk - fy, wy0 = yh - yk;
            int jx0 = dx + 3, jx1 = dx + 4;
            int jy0 = dy + 3, jy1 = dy + 4;
            float val = wx0 * wy0 * D[jy0 * 8 + jx0] + wx0 * wy1 * D[jy1 * 8 + jx0] +
                        wx1 * wy0 * D[jy0 * 8 + jx1] + wx1 * wy1 * D[jy1 * 8 + jx1];
            out[((size_t)b * NQ + n) * (NLEV * NK) + l * NK + tid] = val;
        }
        __syncthreads();
    }
}

extern "C" void kernel_launch(void* const* d_in, const int* in_sizes, int n_in,
                              void* d_out, int out_size) {
    const float* fmap1   = (const float*)d_in[0];
    const float* fmap2   = (const float*)d_in[1];
    const float* coords1 = (const float*)d_in[2];
    const float* coords2 = (const float*)d_in[3];
    float* out = (float*)d_out;

    float *pyr1, *pyr2, *pyr3;
    __half *h0, *h1, *h2, *h3;
    cudaGetSymbolAddress((void**)&pyr1, g_pyr1);
    cudaGetSymbolAddress((void**)&pyr2, g_pyr2);
    cudaGetSymbolAddress((void**)&pyr3, g_pyr3);
    cudaGetSymbolAddress((void**)&h0, g_h0);
    cudaGetSymbolAddress((void**)&h1, g_h1);
    cudaGetSymbolAddress((void**)&h2, g_h2);
    cudaGetSymbolAddress((void**)&h3, g_h3);

    // Cascaded pyramid (un-normalized fp32).
    downsample_kernel<<<dim3(32 * 32, NB), 256>>>(fmap2, pyr1, 64, 64);
    downsample_kernel<<<dim3(16 * 16, NB), 256>>>(pyr1, pyr2, 32, 32);
    downsample_kernel<<<dim3(8 * 8, NB), 256>>>(pyr2, pyr3, 16, 16);

    // Per-level L2 normalization -> fp16 (warp per pixel, 8 pixels/block).
    normalize_h_kernel<<<dim3(64 * 64 / 8, NB), 256>>>(fmap2, h0, 64 * 64);
    normalize_h_kernel<<<dim3(32 * 32 / 8, NB), 256>>>(pyr1, h1, 32 * 32);
    normalize_h_kernel<<<dim3(16 * 16 / 8, NB), 256>>>(pyr2, h2, 16 * 16);
    normalize_h_kernel<<<dim3(8 * 8 / 8, NB), 256>>>(pyr3, h3, 8 * 8);

    // Main correlation kernel: one block per (b, n).
    corr_kernel<<<dim3(NQ, NB), 256>>>(fmap1, coords1, coords2,
                                       h0, h1, h2, h3, out);
}

// round 6
// speedup vs baseline: 1.5777x; 1.3051x over previous
#include <cuda_runtime.h>
#include <cuda_fp16.h>
#include <math.h>

#define NB 2
#define NH 64
#define NW 64
#define NC 256
#define NQ 4096
#define NK 49
#define NLEV 4

// Packed pyramid scratch (levels 1..3, un-normalized fp32) and fp16 normalized.
// Region offsets (in pixels): L1 at 0, L2 at NB*1024, L3 at NB*1024+NB*256.
#define PYR_PX (NB * (32*32 + 16*16 + 8*8))
__device__ float  g_pyrA[PYR_PX * NC];
__device__ __half g_h0[NB*64*64*NC];
__device__ __half g_hA[PYR_PX * NC];

#define OFF_L1 0
#define OFF_L2 (NB * 32 * 32)
#define OFF_L3 (NB * (32*32 + 16*16))

__device__ __forceinline__ unsigned int h2_as_u32(__half2 h) {
    return *reinterpret_cast<unsigned int*>(&h);
}

// jax.image.resize(method='bilinear', antialias=True) 2x downsample taps.
__device__ __forceinline__ void resize_taps(int i, int n, int jj[4], float ww[4]) {
    float c = 2.0f * (float)i + 0.5f;
    float s = 0.0f;
#pragma unroll
    for (int t = 0; t < 4; t++) {
        int j = 2 * i - 1 + t;
        float w = 0.0f;
        if (j >= 0 && j < n) w = 1.0f - 0.5f * fabsf(c - (float)j);
        jj[t] = j < 0 ? 0 : (j > n - 1 ? n - 1 : j);
        ww[t] = w;
        s += w;
    }
    float inv = 1.0f / s;
#pragma unroll
    for (int t = 0; t < 4; t++) ww[t] *= inv;
}

__global__ void downsample_kernel(const float* __restrict__ in, float* __restrict__ out,
                                  int Hi, int Wi) {
    int Ho = Hi >> 1, Wo = Wi >> 1;
    int p = blockIdx.x;
    int b = blockIdx.y;
    int yo = p / Wo, xo = p % Wo;
    int c = threadIdx.x;
    int jy[4], jx[4];
    float wy[4], wx[4];
    resize_taps(yo, Hi, jy, wy);
    resize_taps(xo, Wi, jx, wx);
    const float* ib = in + (size_t)b * Hi * Wi * NC;
    float acc = 0.0f;
#pragma unroll
    for (int a = 0; a < 4; a++) {
        float r = 0.0f;
#pragma unroll
        for (int t = 0; t < 4; t++)
            r += wx[t] * ib[((size_t)jy[a] * Wi + jx[t]) * NC + c];
        acc += wy[a] * r;
    }
    out[(((size_t)b * Ho + yo) * Wo + xo) * NC + c] = acc;
}

// Warp-per-pixel L2 normalize, fp32 in -> fp16 out, flat pixel indexing.
__global__ void __launch_bounds__(256) normalize_h_kernel(
    const float* __restrict__ in, __half* __restrict__ out) {
    int warp = threadIdx.x >> 5, lane = threadIdx.x & 31;
    int p = blockIdx.x * 8 + warp;
    size_t base = (size_t)p * NC;
    const float4* ip = (const float4*)(in + base);
    float4 a0 = ip[lane * 2];
    float4 a1 = ip[lane * 2 + 1];
    float s = a0.x*a0.x + a0.y*a0.y + a0.z*a0.z + a0.w*a0.w +
              a1.x*a1.x + a1.y*a1.y + a1.z*a1.z + a1.w*a1.w;
#pragma unroll
    for (int o = 16; o > 0; o >>= 1) s += __shfl_xor_sync(0xffffffffu, s, o);
    float inv = 1.0f / (sqrtf(s) + 1e-6f);
    __half2 h0 = __floats2half2_rn(a0.x * inv, a0.y * inv);
    __half2 h1 = __floats2half2_rn(a0.z * inv, a0.w * inv);
    __half2 h2 = __floats2half2_rn(a1.x * inv, a1.y * inv);
    __half2 h3 = __floats2half2_rn(a1.z * inv, a1.w * inv);
    uint4 pk;
    pk.x = h2_as_u32(h0); pk.y = h2_as_u32(h1);
    pk.z = h2_as_u32(h2); pk.w = h2_as_u32(h3);
    ((uint4*)(out + base))[lane] = pk;
}

// Main kernel: one block per (b, n) query. 256 threads.
__global__ void __launch_bounds__(256) corr_kernel(
    const float* __restrict__ fmap1,
    const float* __restrict__ coords1,
    const float* __restrict__ coords2,
    const __half* __restrict__ h0,
    const __half* __restrict__ hA,
    float* __restrict__ out) {
    int b = blockIdx.y;
    int n = blockIdx.x;
    int tid = threadIdx.x;
    int lane = tid & 31, wid = tid >> 5;

    __shared__ float feat1[NC];
    __shared__ float D[NLEV][64];
    __shared__ float red[8];
    __shared__ float sscale;

    // ---- Stage A: feat1 = normalize(bilinear(fmap1, coords1)) ----
    float cx = coords1[((size_t)b * NQ + n) * 2 + 0];
    float cy = coords1[((size_t)b * NQ + n) * 2 + 1];
    int fx0 = (int)floorf(cx);
    int fy0 = (int)floorf(cy);
    int x0 = min(max(fx0, 0), NW - 1);
    int x1 = min(max(fx0 + 1, 0), NW - 1);
    int y0 = min(max(fy0, 0), NH - 1);
    int y1 = min(max(fy0 + 1, 0), NH - 1);
    float x0f = (float)x0, x1f = (float)x1, y0f = (float)y0, y1f = (float)y1;
    float wa = (x1f - cx) * (y1f - cy);
    float wb = (x1f - cx) * (cy - y0f);
    float wc = (cx - x0f) * (y1f - cy);
    float wd = (cx - x0f) * (cy - y0f);
    const float* fb1 = fmap1 + (size_t)b * NH * NW * NC;
    // L2-only loads: keep L1 clean for level-2/3 feature rows.
    float v = wa * __ldcg(&fb1[((size_t)y0 * NW + x0) * NC + tid]) +
              wb * __ldcg(&fb1[((size_t)y1 * NW + x0) * NC + tid]) +
              wc * __ldcg(&fb1[((size_t)y0 * NW + x1) * NC + tid]) +
              wd * __ldcg(&fb1[((size_t)y1 * NW + x1) * NC + tid]);
    float s = v * v;
#pragma unroll
    for (int o = 16; o > 0; o >>= 1) s += __shfl_xor_sync(0xffffffffu, s, o);
    if (lane == 0) red[wid] = s;
    __syncthreads();
    if (tid == 0) {
        float t = 0.0f;
#pragma unroll
        for (int i = 0; i < 8; i++) t += red[i];
        sscale = 1.0f / (sqrtf(t) + 1e-6f);
    }
    __syncthreads();
    feat1[tid] = v * sscale;
    __syncthreads();

    float qx = coords2[((size_t)b * NQ + n) * 2 + 0];
    float qy = coords2[((size_t)b * NQ + n) * 2 + 1];

    const __half* levels[NLEV] = {
        h0 + (size_t)b * 64 * 64 * NC,
        hA + ((size_t)OFF_L1 + (size_t)b * 32 * 32) * NC,
        hA + ((size_t)OFF_L2 + (size_t)b * 16 * 16) * NC,
        hA + ((size_t)OFF_L3 + (size_t)b * 8 * 8) * NC};

    // Per-lane query slice: channels lane*8 .. lane*8+7.
    float q[8];
    {
        const float4* f1p = (const float4*)feat1;
        float4 t0 = f1p[lane * 2];
        float4 t1 = f1p[lane * 2 + 1];
        q[0] = t0.x; q[1] = t0.y; q[2] = t0.z; q[3] = t0.w;
        q[4] = t1.x; q[5] = t1.y; q[6] = t1.z; q[7] = t1.w;
    }

#pragma unroll
    for (int l = 0; l < NLEV; l++) {
        const int Hl = NH >> l, Wl = NW >> l;
        const __half* fb = levels[l];
        float bx = qx * (1.0f / (float)(1 << l));
        float by = qy * (1.0f / (float)(1 << l));
        int ix = (int)floorf(bx);
        int iy = (int)floorf(by);

        // Warp `wid` owns window row `wid`: 8 dots, one per column.
        int yy = min(max(iy - 3 + wid, 0), Hl - 1);
        const uint4* rowbase = (const uint4*)(fb + (size_t)yy * Wl * NC);
        float acc[8];
#pragma unroll
        for (int wj = 0; wj < 8; wj++) {
            int xx = min(max(ix - 3 + wj, 0), Wl - 1);
            // Levels 0/1: L2-only (one-touch stream). Levels 2/3: allow L1 (hot set).
            uint4 r = (l < 2) ? __ldcg(&rowbase[xx * (NC / 8) + lane])
                              : __ldg(&rowbase[xx * (NC / 8) + lane]);
            float2 f0 = __half22float2(*(const __half2*)&r.x);
            float2 f1 = __half22float2(*(const __half2*)&r.y);
            float2 f2 = __half22float2(*(const __half2*)&r.z);
            float2 f3 = __half22float2(*(const __half2*)&r.w);
            acc[wj] = f0.x*q[0] + f0.y*q[1] + f1.x*q[2] + f1.y*q[3] +
                      f2.x*q[4] + f2.y*q[5] + f3.x*q[6] + f3.y*q[7];
        }
        // Multi-value butterfly: 8 sums across 32 lanes in 16 shuffles.
        // After bit-b steps, lane owns position p = 4*bit0 + 2*bit1 + 1*bit2.
#pragma unroll
        for (int j = 0; j < 4; j++) {
            float t0 = __shfl_xor_sync(0xffffffffu, acc[j], 1);
            float t1 = __shfl_xor_sync(0xffffffffu, acc[j + 4], 1);
            acc[j] = (lane & 1) ? (acc[j + 4] + t1) : (acc[j] + t0);
        }
#pragma unroll
        for (int j = 0; j < 2; j++) {
            float t0 = __shfl_xor_sync(0xffffffffu, acc[j], 2);
            float t1 = __shfl_xor_sync(0xffffffffu, acc[j + 2], 2);
            acc[j] = (lane & 2) ? (acc[j + 2] + t1) : (acc[j] + t0);
        }
        {
            float t0 = __shfl_xor_sync(0xffffffffu, acc[0], 4);
            float t1 = __shfl_xor_sync(0xffffffffu, acc[1], 4);
            acc[0] = (lane & 4) ? (acc[1] + t1) : (acc[0] + t0);
        }
        acc[0] += __shfl_xor_sync(0xffffffffu, acc[0], 8);
        acc[0] += __shfl_xor_sync(0xffffffffu, acc[0], 16);
        int p = ((lane & 1) << 2) | (lane & 2) | ((lane >> 2) & 1);
        if (lane < 8) D[l][wid * 8 + p] = acc[0];
    }
    __syncthreads();

    // ---- Fused blend: 196 threads produce all 4*49 outputs ----
    if (tid < NLEV * NK) {
        int l = tid / NK;
        int k = tid - l * NK;
        int Hl = NH >> l, Wl = NW >> l;
        float bx = qx * (1.0f / (float)(1 << l));
        float by = qy * (1.0f / (float)(1 << l));
        int dy = k / 7 - 3;   // offs is dy-major
        int dx = k % 7 - 3;
        float xk = fminf(fmaxf(bx + (float)dx, 0.0f), (float)(Wl - 1));
        float yk = fminf(fmaxf(by + (float)dy, 0.0f), (float)(Hl - 1));
        float fx = floorf(xk), fy = floorf(yk);
        float xh = fminf(fx + 1.0f, (float)(Wl - 1));
        float yh = fminf(fy + 1.0f, (float)(Hl - 1));
        float wx1 = xk - fx, wx0 = xh - xk;
        float wy1 = yk - fy, wy0 = yh - yk;
        int jx0 = dx + 3, jx1 = dx + 4;
        int jy0 = dy + 3, jy1 = dy + 4;
        float val = wx0 * wy0 * D[l][jy0 * 8 + jx0] + wx0 * wy1 * D[l][jy1 * 8 + jx0] +
                    wx1 * wy0 * D[l][jy0 * 8 + jx1] + wx1 * wy1 * D[l][jy1 * 8 + jx1];
        out[((size_t)b * NQ + n) * (NLEV * NK) + tid] = val;
    }
}

extern "C" void kernel_launch(void* const* d_in, const int* in_sizes, int n_in,
                              void* d_out, int out_size) {
    const float* fmap1   = (const float*)d_in[0];
    const float* fmap2   = (const float*)d_in[1];
    const float* coords1 = (const float*)d_in[2];
    const float* coords2 = (const float*)d_in[3];
    float* out = (float*)d_out;

    float* pyrA;
    __half *h0, *hA;
    cudaGetSymbolAddress((void**)&pyrA, g_pyrA);
    cudaGetSymbolAddress((void**)&h0, g_h0);
    cudaGetSymbolAddress((void**)&hA, g_hA);

    float* pyr1 = pyrA + (size_t)OFF_L1 * NC;
    float* pyr2 = pyrA + (size_t)OFF_L2 * NC;
    float* pyr3 = pyrA + (size_t)OFF_L3 * NC;

    // Cascaded pyramid (un-normalized fp32): 3 launches.
    downsample_kernel<<<dim3(32 * 32, NB), 256>>>(fmap2, pyr1, 64, 64);
    downsample_kernel<<<dim3(16 * 16, NB), 256>>>(pyr1, pyr2, 32, 32);
    downsample_kernel<<<dim3(8 * 8, NB), 256>>>(pyr2, pyr3, 16, 16);

    // Normalization -> fp16: 2 launches (level 0, then packed levels 1-3).
    normalize_h_kernel<<<NB * 64 * 64 / 8, 256>>>(fmap2, h0);
    normalize_h_kernel<<<PYR_PX / 8, 256>>>(pyrA, hA);

    // Main correlation kernel (launch #5 -> profiled by ncu -s 5 -c 1).
    corr_kernel<<<dim3(NQ, NB), 256>>>(fmap1, coords1, coords2, h0, hA, out);
}